// round 1
// baseline (speedup 1.0000x reference)
#include <cuda_runtime.h>
#include <math.h>

#define EPSF    1e-8f
#define LAMBDAF 1e-3f
#define NTH 512
#define NW  16
#define BPW 18    // 288 / 16 warps

// smem float counts
//  s_xr 4608 | s_a 288 | s_r 9216 | s_p1 8192 | s_p2 8192 | s_rsum 32 | s_invr 32
//  s_mu 512 | s_i2s 512 | s_hls 512 | s_lna 32 | s_aout 32   => 32160 floats = 128640 B
#define SMEM_FLOATS 32160

__device__ __forceinline__ float warp_sum(float v) {
    #pragma unroll
    for (int o = 16; o; o >>= 1) v += __shfl_xor_sync(0xffffffffu, v, o);
    return v;
}
__device__ __forceinline__ float warp_max(float v) {
    #pragma unroll
    for (int o = 16; o; o >>= 1) v = fmaxf(v, __shfl_xor_sync(0xffffffffu, v, o));
    return v;
}

__global__ void __launch_bounds__(NTH, 1)
emcaps_kernel(const float* __restrict__ x,
              const float* __restrict__ Wt,
              const float* __restrict__ beta_u,
              const float* __restrict__ beta_a,
              float* __restrict__ out_main,
              float* __restrict__ out_r)
{
    extern __shared__ float sm[];
    float* s_xr   = sm;              // [288*16]  patch matrices
    float* s_a    = s_xr + 4608;     // [288]     a_in
    float* s_r    = s_a  + 288;      // [288*32]  routing
    float* s_p1   = s_r  + 9216;     // [16*512]  per-warp partials (mu)
    float* s_p2   = s_p1 + 8192;     // [16*512]  per-warp partials (E[v^2])
    float* s_rsum = s_p2 + 8192;     // [32]
    float* s_invr = s_rsum + 32;     // [32]
    float* s_mu   = s_invr + 32;     // [512] layout [p][c]
    float* s_i2s  = s_mu  + 512;     // [512] 1/(2 sigma)  [p][c]
    float* s_hls  = s_i2s + 512;     // [512] 0.5*ln(sigma) [p][c]
    float* s_lna  = s_hls + 512;     // [32]  ln(a_out) - sum_p hls  (e-step const)
    float* s_aout = s_lna + 32;      // [32]

    const int n   = blockIdx.x;      // 508
    const int tid = threadIdx.x;
    const int w   = tid >> 5;        // warp id
    const int c   = tid & 31;        // output capsule (lane)

    // ---- load the 9 patch rows: g = 9n+q -> x[b, k1+j, 0, :] ----
    for (int idx = tid; idx < 9 * 544; idx += NTH) {
        int q  = idx / 544;
        int rr = idx - q * 544;
        int g  = n * 9 + q;
        int b  = g / 2286;
        int k1 = (g - b * 2286) / 762;
        int j  = g % 254;
        const float* row = x + (size_t)((b * 256 + (k1 + j)) * 4) * 544;  // h = 0
        float val = row[rr];
        if (rr < 512) s_xr[q * 512 + rr] = val;
        else          s_a [q * 32 + rr - 512] = val;
    }
    for (int idx = tid; idx < 9216; idx += NTH) s_r[idx] = (1.0f / 32.0f);
    __syncthreads();

    for (int it = 0; it < 3; ++it) {
        // ================= m-step phase 1: r <- normalize(r * a_in) =================
        float prs = 0.f;
        #pragma unroll 2
        for (int bi = 0; bi < BPW; ++bi) {
            int B = w * BPW + bi;
            float rv  = s_r[B * 32 + c] * s_a[B];
            float den = warp_sum(rv) + EPSF;
            float rr  = rv / den;
            s_r[B * 32 + c] = rr;
            prs += rr;
        }
        s_p1[w * 32 + c] = prs;
        __syncthreads();
        if (tid < 32) {
            float t = 0.f;
            #pragma unroll
            for (int ww = 0; ww < NW; ++ww) t += s_p1[ww * 32 + tid];
            s_rsum[tid] = t;
            s_invr[tid] = 1.0f / (t + EPSF);
        }
        __syncthreads();

        // ================= m-step phase 2: weighted moments over B =================
        float acc1[16], acc2[16];
        #pragma unroll
        for (int p = 0; p < 16; ++p) { acc1[p] = 0.f; acc2[p] = 0.f; }
        const float invc = s_invr[c];
        #pragma unroll 2
        for (int bi = 0; bi < BPW; ++bi) {
            int B = w * BPW + bi;
            const float4* wp  = reinterpret_cast<const float4*>(Wt) + (size_t)(B * 32 + c) * 4;
            float4 w0 = wp[0], w1 = wp[1], w2 = wp[2], w3 = wp[3];
            const float4* xp4 = reinterpret_cast<const float4*>(s_xr + B * 16);
            float coeff = s_r[B * 32 + c] * invc;
            #pragma unroll
            for (int i = 0; i < 4; ++i) {
                float4 xi = xp4[i];
                float v0 = xi.x * w0.x + xi.y * w1.x + xi.z * w2.x + xi.w * w3.x;
                float v1 = xi.x * w0.y + xi.y * w1.y + xi.z * w2.y + xi.w * w3.y;
                float v2 = xi.x * w0.z + xi.y * w1.z + xi.z * w2.z + xi.w * w3.z;
                float v3 = xi.x * w0.w + xi.y * w1.w + xi.z * w2.w + xi.w * w3.w;
                acc1[4*i+0] += coeff * v0;  acc2[4*i+0] += coeff * v0 * v0;
                acc1[4*i+1] += coeff * v1;  acc2[4*i+1] += coeff * v1 * v1;
                acc1[4*i+2] += coeff * v2;  acc2[4*i+2] += coeff * v2 * v2;
                acc1[4*i+3] += coeff * v3;  acc2[4*i+3] += coeff * v3 * v3;
            }
        }
        {
            float4* p1v = reinterpret_cast<float4*>(s_p1 + w * 512 + c * 16);
            float4* p2v = reinterpret_cast<float4*>(s_p2 + w * 512 + c * 16);
            #pragma unroll
            for (int i = 0; i < 4; ++i) {
                p1v[i] = make_float4(acc1[4*i], acc1[4*i+1], acc1[4*i+2], acc1[4*i+3]);
                p2v[i] = make_float4(acc2[4*i], acc2[4*i+1], acc2[4*i+2], acc2[4*i+3]);
            }
        }
        __syncthreads();

        // ---- reduce partials, compute mu / sigma / a_out ----
        {
            int cp = tid;              // cp = c2*16 + p
            int c2 = cp >> 4, p = cp & 15;
            float e1 = 0.f, e2 = 0.f;
            #pragma unroll
            for (int ww = 0; ww < NW; ++ww) {
                e1 += s_p1[ww * 512 + cp];
                e2 += s_p2[ww * 512 + cp];
            }
            float S   = s_rsum[c2] * s_invr[c2];       // sum of coeff over B
            float mu  = e1;
            float var = e2 - 2.f * mu * e1 + mu * mu * S;
            float sig = fmaxf(var, 0.f) + EPSF;
            float hls = 0.5f * __logf(sig);
            s_mu [p * 32 + c2] = mu;
            s_i2s[p * 32 + c2] = 0.5f / sig;
            s_hls[p * 32 + c2] = hls;
            // reduce hls over p (16-lane segments)
            float hsum = hls;
            #pragma unroll
            for (int o = 8; o; o >>= 1) hsum += __shfl_xor_sync(0xffffffffu, hsum, o, 16);
            if (p == 0) {
                float cost = s_rsum[c2] * (16.f * beta_u[c2] + hsum);
                float av = 1.0f / (1.0f + __expf(-LAMBDAF * (beta_a[c2] - cost)));
                s_aout[c2] = av;
                s_lna [c2] = __logf(av) - hsum;   // e-step per-c constant
            }
        }
        __syncthreads();

        if (it == 2) break;

        // ================= e-step: r <- softmax_c( ln_ap ) =================
        const float lnac = s_lna[c];
        #pragma unroll 2
        for (int bi = 0; bi < BPW; ++bi) {
            int B = w * BPW + bi;
            const float4* wp  = reinterpret_cast<const float4*>(Wt) + (size_t)(B * 32 + c) * 4;
            float4 w0 = wp[0], w1 = wp[1], w2 = wp[2], w3 = wp[3];
            const float4* xp4 = reinterpret_cast<const float4*>(s_xr + B * 16);
            float sc = lnac;
            #pragma unroll
            for (int i = 0; i < 4; ++i) {
                float4 xi = xp4[i];
                float v0 = xi.x * w0.x + xi.y * w1.x + xi.z * w2.x + xi.w * w3.x;
                float v1 = xi.x * w0.y + xi.y * w1.y + xi.z * w2.y + xi.w * w3.y;
                float v2 = xi.x * w0.z + xi.y * w1.z + xi.z * w2.z + xi.w * w3.z;
                float v3 = xi.x * w0.w + xi.y * w1.w + xi.z * w2.w + xi.w * w3.w;
                float d0 = v0 - s_mu[(4*i+0) * 32 + c];
                float d1 = v1 - s_mu[(4*i+1) * 32 + c];
                float d2 = v2 - s_mu[(4*i+2) * 32 + c];
                float d3 = v3 - s_mu[(4*i+3) * 32 + c];
                sc -= d0 * d0 * s_i2s[(4*i+0) * 32 + c];
                sc -= d1 * d1 * s_i2s[(4*i+1) * 32 + c];
                sc -= d2 * d2 * s_i2s[(4*i+2) * 32 + c];
                sc -= d3 * d3 * s_i2s[(4*i+3) * 32 + c];
            }
            float m  = warp_max(sc);
            float e  = __expf(sc - m);
            float ds = warp_sum(e);
            float rn = e / ds;
            s_r[B * 32 + c] = rn;
            if (it == 1) out_r[(size_t)n * 9216 + B * 32 + c] = rn;  // returned r
        }
        __syncthreads();
    }

    // ---- final outputs: out[n, 0:512] = mu (c-major), out[n, 512:544] = a_out ----
    out_main[(size_t)n * 544 + tid] = s_mu[(tid & 15) * 32 + (tid >> 4)];
    if (tid < 32) out_main[(size_t)n * 544 + 512 + tid] = s_aout[tid];
}

extern "C" void kernel_launch(void* const* d_in, const int* in_sizes, int n_in,
                              void* d_out, int out_size) {
    const float* x  = (const float*)d_in[0];
    const float* Wt = (const float*)d_in[1];
    const float* bu = (const float*)d_in[2];
    const float* ba = (const float*)d_in[3];
    float* out  = (float*)d_out;
    float* outr = out + (size_t)2 * 254 * 544;   // 276352 floats of `out`, then `r`

    const int smem_bytes = SMEM_FLOATS * 4;
    cudaFuncSetAttribute(emcaps_kernel, cudaFuncAttributeMaxDynamicSharedMemorySize, smem_bytes);
    emcaps_kernel<<<508, NTH, smem_bytes>>>(x, Wt, bu, ba, out, outr);
}

// round 2
// speedup vs baseline: 1.8306x; 1.8306x over previous
#include <cuda_runtime.h>
#include <math.h>

#define EPSF    1e-8f
#define LAMBDAF 1e-3f
#define NTH 512
#define NW  16
#define BPW 18    // 288 / 16 warps

// smem floats: xr 4608 | fac 288 | p1 8192 | p2 8192 | prs 512 | mu 512 | i2s 512 | lna 32 | aout 32
#define SMEM_FLOATS (4608 + 288 + 8192 + 8192 + 512 + 512 + 512 + 32 + 32)

__device__ __forceinline__ float warp_sum(float v) {
    #pragma unroll
    for (int o = 16; o; o >>= 1) v += __shfl_xor_sync(0xffffffffu, v, o);
    return v;
}
__device__ __forceinline__ float warp_max(float v) {
    #pragma unroll
    for (int o = 16; o; o >>= 1) v = fmaxf(v, __shfl_xor_sync(0xffffffffu, v, o));
    return v;
}

__global__ void __launch_bounds__(NTH, 1)
emcaps_kernel(const float* __restrict__ x,
              const float* __restrict__ Wt,
              const float* __restrict__ beta_u,
              const float* __restrict__ beta_a,
              float* __restrict__ out_main,
              float* __restrict__ out_r)
{
    extern __shared__ float sm[];
    float* s_xr   = sm;               // [288*16] patch matrices (row-broadcast)
    float* s_fac  = s_xr  + 4608;     // [288]    a_in/(a_in+eps)  (phase-1 folded)
    float* s_p1   = s_fac + 288;      // [16*512] per-warp partials  Σ r2*v
    float* s_p2   = s_p1  + 8192;     // [16*512] per-warp partials  Σ r2*v^2
    float* s_prs  = s_p2  + 8192;     // [16*32]  per-warp partials  Σ r2
    float* s_mu   = s_prs + 512;      // [512] layout [p][c]
    float* s_i2s  = s_mu  + 512;      // [512] 1/(2 sigma)   [p][c]
    float* s_lna  = s_i2s + 512;      // [32]  ln(a_out) - Σ_p 0.5 ln σ
    float* s_aout = s_lna + 32;       // [32]

    const int n   = blockIdx.x;       // 508
    const int tid = threadIdx.x;
    const int w   = tid >> 5;         // warp id -> B block
    const int c   = tid & 31;         // output capsule (lane)

    // ---- load the 9 patch rows: g = 9n+q -> x[b, k1+j, 0, :] ----
    for (int idx = tid; idx < 9 * 544; idx += NTH) {
        int q  = idx / 544;
        int rr = idx - q * 544;
        int g  = n * 9 + q;
        int b  = g / 2286;
        int k1 = (g - b * 2286) / 762;
        int j  = g % 254;
        const float* row = x + (size_t)((b * 256 + (k1 + j)) * 4) * 544;  // h = 0
        float val = row[rr];
        if (rr < 512) s_xr[q * 512 + rr] = val;
        else          s_fac[q * 32 + rr - 512] = val / (val + EPSF);
    }
    __syncthreads();

    float rmu[16], ri2s[16];
    float lnac = 0.f;
    #pragma unroll
    for (int p = 0; p < 16; ++p) { rmu[p] = 0.f; ri2s[p] = 0.f; }

    for (int s = 0; s < 3; ++s) {
        // ============ fused sweep: (e-step softmax) + phase-1 + moment accumulation ============
        float acc1[16], acc2[16];
        #pragma unroll
        for (int p = 0; p < 16; ++p) { acc1[p] = 0.f; acc2[p] = 0.f; }
        float prs = 0.f;

        #pragma unroll 2
        for (int bi = 0; bi < BPW; ++bi) {
            int B = w * BPW + bi;
            const float4* wp  = reinterpret_cast<const float4*>(Wt) + (size_t)(B * 32 + c) * 4;
            float4 w0 = wp[0], w1 = wp[1], w2 = wp[2], w3 = wp[3];
            const float4* xp4 = reinterpret_cast<const float4*>(s_xr + B * 16);

            float v[16];
            #pragma unroll
            for (int i = 0; i < 4; ++i) {
                float4 xi = xp4[i];
                v[4*i+0] = xi.x * w0.x + xi.y * w1.x + xi.z * w2.x + xi.w * w3.x;
                v[4*i+1] = xi.x * w0.y + xi.y * w1.y + xi.z * w2.y + xi.w * w3.y;
                v[4*i+2] = xi.x * w0.z + xi.y * w1.z + xi.z * w2.z + xi.w * w3.z;
                v[4*i+3] = xi.x * w0.w + xi.y * w1.w + xi.z * w2.w + xi.w * w3.w;
            }

            float r2;
            if (s == 0) {
                r2 = s_fac[B] * (1.0f / 32.0f);          // uniform r, normalized by a_in
            } else {
                float sc = lnac;
                #pragma unroll
                for (int p = 0; p < 16; ++p) {
                    float d = v[p] - rmu[p];
                    sc = fmaf(-d * d, ri2s[p], sc);
                }
                float m  = warp_max(sc);
                float e  = __expf(sc - m);
                float ds = warp_sum(e);
                float r  = e / ds;                       // e-step softmax result
                if (s == 2) out_r[(size_t)n * 9216 + B * 32 + c] = r;
                r2 = r * s_fac[B];                       // phase-1: softmax sums to 1 -> den = a+eps
            }

            prs += r2;
            #pragma unroll
            for (int p = 0; p < 16; ++p) {
                acc1[p] = fmaf(r2, v[p], acc1[p]);
                acc2[p] = fmaf(r2 * v[p], v[p], acc2[p]);
            }
        }

        // store per-warp partials
        {
            float4* p1v = reinterpret_cast<float4*>(s_p1 + w * 512 + c * 16);
            float4* p2v = reinterpret_cast<float4*>(s_p2 + w * 512 + c * 16);
            #pragma unroll
            for (int i = 0; i < 4; ++i) {
                p1v[i] = make_float4(acc1[4*i], acc1[4*i+1], acc1[4*i+2], acc1[4*i+3]);
                p2v[i] = make_float4(acc2[4*i], acc2[4*i+1], acc2[4*i+2], acc2[4*i+3]);
            }
            s_prs[w * 32 + c] = prs;
        }
        __syncthreads();

        // ============ reduce partials -> mu / sigma / a_out ============
        {
            int cp = tid;                 // cp = c2*16 + p
            int c2 = cp >> 4, p = cp & 15;
            float e1 = 0.f, e2 = 0.f, rs = 0.f;
            #pragma unroll
            for (int ww = 0; ww < NW; ++ww) {
                e1 += s_p1[ww * 512 + cp];
                e2 += s_p2[ww * 512 + cp];
                rs += s_prs[ww * 32 + c2];
            }
            float invr = 1.0f / (rs + EPSF);
            float S    = rs * invr;                     // Σ coeff over B
            float mu   = e1 * invr;
            float E2   = e2 * invr;
            float var  = E2 - mu * mu * (2.0f - S);
            float sig  = fmaxf(var, 0.f) + EPSF;
            float hls  = 0.5f * __logf(sig);
            s_mu [p * 32 + c2] = mu;
            s_i2s[p * 32 + c2] = 0.5f / sig;
            float hsum = hls;
            #pragma unroll
            for (int o = 8; o; o >>= 1) hsum += __shfl_xor_sync(0xffffffffu, hsum, o, 16);
            if (p == 0) {
                float cost = rs * (16.f * beta_u[c2] + hsum);
                float av   = 1.0f / (1.0f + __expf(-LAMBDAF * (beta_a[c2] - cost)));
                s_aout[c2] = av;
                s_lna [c2] = __logf(av) - hsum;         // e-step per-c constant
            }
        }
        __syncthreads();

        if (s < 2) {
            lnac = s_lna[c];
            #pragma unroll
            for (int p = 0; p < 16; ++p) {
                rmu [p] = s_mu [p * 32 + c];
                ri2s[p] = s_i2s[p * 32 + c];
            }
        }
    }

    // ---- final outputs: out[n, 0:512] = mu (c-major), out[n, 512:544] = a_out ----
    out_main[(size_t)n * 544 + tid] = s_mu[(tid & 15) * 32 + (tid >> 4)];
    if (tid < 32) out_main[(size_t)n * 544 + 512 + tid] = s_aout[tid];
}

extern "C" void kernel_launch(void* const* d_in, const int* in_sizes, int n_in,
                              void* d_out, int out_size) {
    const float* x  = (const float*)d_in[0];
    const float* Wt = (const float*)d_in[1];
    const float* bu = (const float*)d_in[2];
    const float* ba = (const float*)d_in[3];
    float* out  = (float*)d_out;
    float* outr = out + (size_t)2 * 254 * 544;   // 276352 floats of `out`, then `r`

    const int smem_bytes = SMEM_FLOATS * 4;
    cudaFuncSetAttribute(emcaps_kernel, cudaFuncAttributeMaxDynamicSharedMemorySize, smem_bytes);
    emcaps_kernel<<<508, NTH, smem_bytes>>>(x, Wt, bu, ba, out, outr);
}

// round 5
// speedup vs baseline: 1.9231x; 1.0506x over previous
#include <cuda_runtime.h>
#include <math.h>

#define EPSF    1e-8f
#define LAMBDAF 1e-3f
#define NTH 512
#define NW  16
#define BPW 18    // 288 / 16 warps

// smem floats: xr 4608 | fac 288 | p1 8192 | p2 8192 | prs 512 | mu 512 | i2s 512 | lna 32 | aout 32
#define SMEM_FLOATS (4608 + 288 + 8192 + 8192 + 512 + 512 + 512 + 32 + 32)

typedef unsigned long long u64t;

__device__ __forceinline__ u64t pack2(float a, float b) {
    u64t r; asm("mov.b64 %0,{%1,%2};" : "=l"(r) : "f"(a), "f"(b)); return r;
}
__device__ __forceinline__ u64t dup2(float a) { return pack2(a, a); }
__device__ __forceinline__ void unpack2(u64t v, float& a, float& b) {
    asm("mov.b64 {%0,%1},%2;" : "=f"(a), "=f"(b) : "l"(v));
}
__device__ __forceinline__ u64t fma2(u64t a, u64t b, u64t c) {
    u64t d; asm("fma.rn.f32x2 %0,%1,%2,%3;" : "=l"(d) : "l"(a), "l"(b), "l"(c)); return d;
}
__device__ __forceinline__ u64t mul2(u64t a, u64t b) {
    u64t d; asm("mul.rn.f32x2 %0,%1,%2;" : "=l"(d) : "l"(a), "l"(b)); return d;
}
__device__ __forceinline__ u64t add2(u64t a, u64t b) {
    u64t d; asm("add.rn.f32x2 %0,%1,%2;" : "=l"(d) : "l"(a), "l"(b)); return d;
}

__device__ __forceinline__ float warp_sum(float v) {
    #pragma unroll
    for (int o = 16; o; o >>= 1) v += __shfl_xor_sync(0xffffffffu, v, o);
    return v;
}

// warp max of f32 via monotonic u32 key + redux.sync.max.u32 (sm_80+; redux.f32 absent on sm_103)
__device__ __forceinline__ float warp_max_f32(float v) {
    unsigned int b = __float_as_uint(v);
    unsigned int key = (b & 0x80000000u) ? ~b : (b | 0x80000000u);
    unsigned int m;
    asm("redux.sync.max.u32 %0, %1, 0xffffffff;" : "=r"(m) : "r"(key));
    unsigned int mb = (m & 0x80000000u) ? (m & 0x7fffffffu) : ~m;
    return __uint_as_float(mb);
}

__global__ void __launch_bounds__(NTH, 1)
emcaps_kernel(const float* __restrict__ x,
              const float* __restrict__ Wt,
              const float* __restrict__ beta_u,
              const float* __restrict__ beta_a,
              float* __restrict__ out_main,
              float* __restrict__ out_r)
{
    extern __shared__ float sm[];
    float* s_xr   = sm;               // [288*16] patch matrices (row-broadcast)
    float* s_fac  = s_xr  + 4608;     // [288]    a_in/(a_in+eps)
    float* s_p1   = s_fac + 288;      // [16*512] per-warp partials Σ r2*v
    float* s_p2   = s_p1  + 8192;     // [16*512] per-warp partials Σ r2*v^2
    float* s_prs  = s_p2  + 8192;     // [16*32]  per-warp partials Σ r2
    float* s_mu   = s_prs + 512;      // [512] layout [p][c]
    float* s_i2s  = s_mu  + 512;      // [512] 1/(2 sigma) [p][c]
    float* s_lna  = s_i2s + 512;      // [32]  ln(a_out) - Σ_p 0.5 ln σ
    float* s_aout = s_lna + 32;       // [32]

    const int n   = blockIdx.x;       // 508
    const int tid = threadIdx.x;
    const int w   = tid >> 5;
    const int c   = tid & 31;

    // ---- load the 9 patch rows: g = 9n+q -> x[b, k1+j, 0, :] ----
    for (int idx = tid; idx < 9 * 544; idx += NTH) {
        int q  = idx / 544;
        int rr = idx - q * 544;
        int g  = n * 9 + q;
        int b  = g / 2286;
        int k1 = (g - b * 2286) / 762;
        int j  = g % 254;
        const float* row = x + (size_t)((b * 256 + (k1 + j)) * 4) * 544;  // h = 0
        float val = row[rr];
        if (rr < 512) s_xr[q * 512 + rr] = val;
        else          s_fac[q * 32 + rr - 512] = val / (val + EPSF);
    }
    __syncthreads();

    u64t nmu2[8], ni2s2[8];
    float lnac = 0.f;
    #pragma unroll
    for (int h = 0; h < 8; ++h) { nmu2[h] = 0ull; ni2s2[h] = 0ull; }

    for (int s = 0; s < 3; ++s) {
        u64t acc1[8], acc2[8];
        #pragma unroll
        for (int h = 0; h < 8; ++h) { acc1[h] = 0ull; acc2[h] = 0ull; }
        float prs = 0.f;

        #pragma unroll 2
        for (int bi = 0; bi < BPW; ++bi) {
            int B = w * BPW + bi;
            // W[B][c] = 16 contiguous floats = 64 bytes = 4 ulonglong2
            const ulonglong2* wp = reinterpret_cast<const ulonglong2*>(Wt) + (size_t)(B * 32 + c) * 4;
            ulonglong2 a0 = wp[0];   // j=0: (k0,k1),(k2,k3)
            ulonglong2 a1 = wp[1];   // j=1
            ulonglong2 a2 = wp[2];   // j=2
            ulonglong2 a3 = wp[3];   // j=3

            const float4* xp4 = reinterpret_cast<const float4*>(s_xr + B * 16);

            u64t vp[8];
            #pragma unroll
            for (int i = 0; i < 4; ++i) {
                float4 xi = xp4[i];
                u64t x0 = dup2(xi.x), x1 = dup2(xi.y), x2 = dup2(xi.z), x3 = dup2(xi.w);
                u64t lo = mul2(x0, a0.x);
                lo = fma2(x1, a1.x, lo);
                lo = fma2(x2, a2.x, lo);
                lo = fma2(x3, a3.x, lo);
                u64t hi = mul2(x0, a0.y);
                hi = fma2(x1, a1.y, hi);
                hi = fma2(x2, a2.y, hi);
                hi = fma2(x3, a3.y, hi);
                vp[2*i]   = lo;   // p = 4i+0, 4i+1
                vp[2*i+1] = hi;   // p = 4i+2, 4i+3
            }

            float r2;
            if (s == 0) {
                r2 = s_fac[B] * (1.0f / 32.0f);
            } else {
                u64t sc2 = 0ull;
                #pragma unroll
                for (int h = 0; h < 8; ++h) {
                    u64t d  = add2(vp[h], nmu2[h]);   // v - mu
                    u64t dd = mul2(d, d);
                    sc2 = fma2(dd, ni2s2[h], sc2);    // -= d^2 / (2 sigma)
                }
                float sl, sh;
                unpack2(sc2, sl, sh);
                float sc = lnac + sl + sh;
                float m  = warp_max_f32(sc);
                float e  = __expf(sc - m);
                float ds = warp_sum(e);
                float r  = e / ds;
                if (s == 2) out_r[(size_t)n * 9216 + B * 32 + c] = r;
                r2 = r * s_fac[B];
            }

            prs += r2;
            u64t r2p = dup2(r2);
            #pragma unroll
            for (int h = 0; h < 8; ++h) {
                u64t t = mul2(r2p, vp[h]);
                acc1[h] = add2(acc1[h], t);
                acc2[h] = fma2(t, vp[h], acc2[h]);
            }
        }

        // store per-warp partials
        {
            ulonglong2* p1v = reinterpret_cast<ulonglong2*>(s_p1 + w * 512 + c * 16);
            ulonglong2* p2v = reinterpret_cast<ulonglong2*>(s_p2 + w * 512 + c * 16);
            #pragma unroll
            for (int i = 0; i < 4; ++i) {
                p1v[i] = make_ulonglong2(acc1[2*i], acc1[2*i+1]);
                p2v[i] = make_ulonglong2(acc2[2*i], acc2[2*i+1]);
            }
            s_prs[w * 32 + c] = prs;
        }
        __syncthreads();

        // ============ reduce partials -> mu / sigma / a_out ============
        {
            int cp = tid;                 // cp = c2*16 + p
            int c2 = cp >> 4, p = cp & 15;
            float e1 = 0.f, e2 = 0.f, rs = 0.f;
            #pragma unroll
            for (int ww = 0; ww < NW; ++ww) {
                e1 += s_p1[ww * 512 + cp];
                e2 += s_p2[ww * 512 + cp];
                rs += s_prs[ww * 32 + c2];
            }
            float invr = 1.0f / (rs + EPSF);
            float S    = rs * invr;
            float mu   = e1 * invr;
            float E2   = e2 * invr;
            float var  = E2 - mu * mu * (2.0f - S);
            float sig  = fmaxf(var, 0.f) + EPSF;
            float hls  = 0.5f * __logf(sig);
            s_mu [p * 32 + c2] = mu;
            s_i2s[p * 32 + c2] = 0.5f / sig;
            float hsum = hls;
            #pragma unroll
            for (int o = 8; o; o >>= 1) hsum += __shfl_xor_sync(0xffffffffu, hsum, o, 16);
            if (p == 0) {
                float cost = rs * (16.f * beta_u[c2] + hsum);
                float av   = 1.0f / (1.0f + __expf(-LAMBDAF * (beta_a[c2] - cost)));
                s_aout[c2] = av;
                s_lna [c2] = __logf(av) - hsum;
            }
        }
        __syncthreads();

        if (s < 2) {
            lnac = s_lna[c];
            #pragma unroll
            for (int h = 0; h < 8; ++h) {
                nmu2 [h] = pack2(-s_mu [(2*h) * 32 + c], -s_mu [(2*h+1) * 32 + c]);
                ni2s2[h] = pack2(-s_i2s[(2*h) * 32 + c], -s_i2s[(2*h+1) * 32 + c]);
            }
        }
    }

    // ---- final outputs ----
    out_main[(size_t)n * 544 + tid] = s_mu[(tid & 15) * 32 + (tid >> 4)];
    if (tid < 32) out_main[(size_t)n * 544 + 512 + tid] = s_aout[tid];
}

extern "C" void kernel_launch(void* const* d_in, const int* in_sizes, int n_in,
                              void* d_out, int out_size) {
    const float* x  = (const float*)d_in[0];
    const float* Wt = (const float*)d_in[1];
    const float* bu = (const float*)d_in[2];
    const float* ba = (const float*)d_in[3];
    float* out  = (float*)d_out;
    float* outr = out + (size_t)2 * 254 * 544;

    const int smem_bytes = SMEM_FLOATS * 4;
    cudaFuncSetAttribute(emcaps_kernel, cudaFuncAttributeMaxDynamicSharedMemorySize, smem_bytes);
    emcaps_kernel<<<508, NTH, smem_bytes>>>(x, Wt, bu, ba, out, outr);
}

// round 6
// speedup vs baseline: 2.1672x; 1.1269x over previous
#include <cuda_runtime.h>
#include <math.h>

#define EPSF    1e-8f
#define LAMBDAF 1e-3f
#define NTH 512
#define NW  16
#define BPW 18    // 288 / 16 warps

// smem floats: xr 4608 | fac 288 | p1 8192 | p2 8192 | prs 512 | mu 512 | i2s 512 | lna 32 | aout 32
#define SMEM_FLOATS (4608 + 288 + 8192 + 8192 + 512 + 512 + 512 + 32 + 32)

typedef unsigned long long u64t;

__device__ __forceinline__ u64t pack2(float a, float b) {
    u64t r; asm("mov.b64 %0,{%1,%2};" : "=l"(r) : "f"(a), "f"(b)); return r;
}
__device__ __forceinline__ u64t dup2(float a) { return pack2(a, a); }
__device__ __forceinline__ void unpack2(u64t v, float& a, float& b) {
    asm("mov.b64 {%0,%1},%2;" : "=f"(a), "=f"(b) : "l"(v));
}
__device__ __forceinline__ u64t fma2(u64t a, u64t b, u64t c) {
    u64t d; asm("fma.rn.f32x2 %0,%1,%2,%3;" : "=l"(d) : "l"(a), "l"(b), "l"(c)); return d;
}
__device__ __forceinline__ u64t mul2(u64t a, u64t b) {
    u64t d; asm("mul.rn.f32x2 %0,%1,%2;" : "=l"(d) : "l"(a), "l"(b)); return d;
}
__device__ __forceinline__ u64t add2(u64t a, u64t b) {
    u64t d; asm("add.rn.f32x2 %0,%1,%2;" : "=l"(d) : "l"(a), "l"(b)); return d;
}

__device__ __forceinline__ float warp_sum(float v) {
    #pragma unroll
    for (int o = 16; o; o >>= 1) v += __shfl_xor_sync(0xffffffffu, v, o);
    return v;
}

// warp max of f32 via monotonic u32 key + redux.sync.max.u32
__device__ __forceinline__ float warp_max_f32(float v) {
    unsigned int b = __float_as_uint(v);
    unsigned int key = (b & 0x80000000u) ? ~b : (b | 0x80000000u);
    unsigned int m;
    asm("redux.sync.max.u32 %0, %1, 0xffffffff;" : "=r"(m) : "r"(key));
    unsigned int mb = (m & 0x80000000u) ? (m & 0x7fffffffu) : ~m;
    return __uint_as_float(mb);
}

__device__ __forceinline__ unsigned int warp_add_u32(unsigned int v) {
    unsigned int s;
    asm("redux.sync.add.u32 %0, %1, 0xffffffff;" : "=r"(s) : "r"(v));
    return s;
}

__global__ void __launch_bounds__(NTH, 1)
emcaps_kernel(const float* __restrict__ x,
              const float* __restrict__ Wt,
              const float* __restrict__ beta_u,
              const float* __restrict__ beta_a,
              float* __restrict__ out_main,
              float* __restrict__ out_r)
{
    extern __shared__ float sm[];
    float* s_xr   = sm;               // [9*512]  patch matrices
    float* s_fac  = s_xr  + 4608;     // [288]    a_in/(a_in+eps)
    float* s_p1   = s_fac + 288;      // [16*512] per-warp partials Σ r2*v
    float* s_p2   = s_p1  + 8192;     // [16*512] per-warp partials Σ r2*v^2
    float* s_prs  = s_p2  + 8192;     // [16*32]  per-warp partials Σ r2
    float* s_mu   = s_prs + 512;      // [512] layout [p][c]
    float* s_i2s  = s_mu  + 512;      // [512] 1/(2 sigma) [p][c]
    float* s_lna  = s_i2s + 512;      // [32]
    float* s_aout = s_lna + 32;       // [32]

    const int n   = blockIdx.x;       // 508
    const int tid = threadIdx.x;
    const int w   = tid >> 5;
    const int c   = tid & 31;

    // ---- load the 9 patch rows: g = 9n+q -> x[b, k1+j, 0, :] ----
    for (int idx = tid; idx < 9 * 544; idx += NTH) {
        int q  = idx / 544;
        int rr = idx - q * 544;
        int g  = n * 9 + q;
        int b  = g / 2286;
        int k1 = (g - b * 2286) / 762;
        int j  = g % 254;
        const float* row = x + (size_t)((b * 256 + (k1 + j)) * 4) * 544;  // h = 0
        float val = row[rr];
        if (rr < 512) s_xr[q * 512 + rr] = val;
        else          s_fac[q * 32 + rr - 512] = val / (val + EPSF);
    }
    __syncthreads();

    u64t nmu2[8], ni2s2[8];
    float lnac = 0.f;
    #pragma unroll
    for (int h = 0; h < 8; ++h) { nmu2[h] = 0ull; ni2s2[h] = 0ull; }

    // W walk: at fixed lane c, consecutive B are 32 blocks of 64 B apart = 128 ulonglong2
    const ulonglong2* wp0 = reinterpret_cast<const ulonglong2*>(Wt) + (size_t)(w * BPW * 32 + c) * 4;

    for (int s = 0; s < 3; ++s) {
        u64t acc1[8], acc2[8];
        #pragma unroll
        for (int h = 0; h < 8; ++h) { acc1[h] = 0ull; acc2[h] = 0ull; }
        float prs = 0.f;

        const ulonglong2* wp = wp0;
        ulonglong2 a0 = wp[0], a1 = wp[1], a2 = wp[2], a3 = wp[3];

        #pragma unroll 2
        for (int bi = 0; bi < BPW; ++bi) {
            int B = w * BPW + bi;

            // prefetch next bi's W before the compute tail
            ulonglong2 b0, b1, b2, b3;
            if (bi + 1 < BPW) {
                const ulonglong2* wn = wp + 128;
                b0 = wn[0]; b1 = wn[1]; b2 = wn[2]; b3 = wn[3];
            } else {
                b0 = a0; b1 = a1; b2 = a2; b3 = a3;
            }

            const float4* xp4 = reinterpret_cast<const float4*>(s_xr + B * 16);

            u64t vp[8];
            #pragma unroll
            for (int i = 0; i < 4; ++i) {
                float4 xi = xp4[i];
                u64t x0 = dup2(xi.x), x1 = dup2(xi.y), x2 = dup2(xi.z), x3 = dup2(xi.w);
                u64t lo = mul2(x0, a0.x);
                lo = fma2(x1, a1.x, lo);
                lo = fma2(x2, a2.x, lo);
                lo = fma2(x3, a3.x, lo);
                u64t hi = mul2(x0, a0.y);
                hi = fma2(x1, a1.y, hi);
                hi = fma2(x2, a2.y, hi);
                hi = fma2(x3, a3.y, hi);
                vp[2*i]   = lo;   // p = 4i+0, 4i+1
                vp[2*i+1] = hi;   // p = 4i+2, 4i+3
            }

            float r2;
            if (s == 0) {
                r2 = s_fac[B] * (1.0f / 32.0f);
            } else {
                u64t sc2 = 0ull;
                #pragma unroll
                for (int h = 0; h < 8; ++h) {
                    u64t d  = add2(vp[h], nmu2[h]);   // v - mu
                    u64t dd = mul2(d, d);
                    sc2 = fma2(dd, ni2s2[h], sc2);    // -= d^2 / (2 sigma)
                }
                float sl, sh;
                unpack2(sc2, sl, sh);
                float sc = lnac + sl + sh;
                float m  = warp_max_f32(sc);
                float e  = __expf(sc - m);
                // fixed-point warp sum: e in (0,1], q <= 2^24, sum <= 2^29
                unsigned int q  = __float2uint_rn(e * 16777216.f);
                unsigned int du = warp_add_u32(q);
                float r  = __fdividef(__uint2float_rn(q), __uint2float_rn(du));
                if (s == 2) out_r[(size_t)n * 9216 + B * 32 + c] = r;
                r2 = r * s_fac[B];
            }

            prs += r2;
            u64t r2p = dup2(r2);
            #pragma unroll
            for (int h = 0; h < 8; ++h) {
                u64t t = mul2(r2p, vp[h]);
                acc1[h] = add2(acc1[h], t);
                acc2[h] = fma2(t, vp[h], acc2[h]);
            }

            a0 = b0; a1 = b1; a2 = b2; a3 = b3;
            wp += 128;
        }

        // store per-warp partials
        {
            ulonglong2* p1v = reinterpret_cast<ulonglong2*>(s_p1 + w * 512 + c * 16);
            ulonglong2* p2v = reinterpret_cast<ulonglong2*>(s_p2 + w * 512 + c * 16);
            #pragma unroll
            for (int i = 0; i < 4; ++i) {
                p1v[i] = make_ulonglong2(acc1[2*i], acc1[2*i+1]);
                p2v[i] = make_ulonglong2(acc2[2*i], acc2[2*i+1]);
            }
            s_prs[w * 32 + c] = prs;
        }
        __syncthreads();

        // ============ reduce partials -> mu / sigma / a_out ============
        {
            int cp = tid;                 // cp = c2*16 + p
            int c2 = cp >> 4, p = cp & 15;
            float e1 = 0.f, e2 = 0.f, rs = 0.f;
            #pragma unroll
            for (int ww = 0; ww < NW; ++ww) {
                e1 += s_p1[ww * 512 + cp];
                e2 += s_p2[ww * 512 + cp];
                rs += s_prs[ww * 32 + c2];
            }
            float invr = 1.0f / (rs + EPSF);
            float S    = rs * invr;
            float mu   = e1 * invr;
            float E2   = e2 * invr;
            float var  = E2 - mu * mu * (2.0f - S);
            float sig  = fmaxf(var, 0.f) + EPSF;
            float hls  = 0.5f * __logf(sig);
            s_mu [p * 32 + c2] = mu;
            s_i2s[p * 32 + c2] = 0.5f / sig;
            float hsum = hls;
            #pragma unroll
            for (int o = 8; o; o >>= 1) hsum += __shfl_xor_sync(0xffffffffu, hsum, o, 16);
            if (p == 0) {
                float cost = rs * (16.f * beta_u[c2] + hsum);
                float av   = 1.0f / (1.0f + __expf(-LAMBDAF * (beta_a[c2] - cost)));
                s_aout[c2] = av;
                s_lna [c2] = __logf(av) - hsum;
            }
        }
        __syncthreads();

        if (s < 2) {
            lnac = s_lna[c];
            #pragma unroll
            for (int h = 0; h < 8; ++h) {
                nmu2 [h] = pack2(-s_mu [(2*h) * 32 + c], -s_mu [(2*h+1) * 32 + c]);
                ni2s2[h] = pack2(-s_i2s[(2*h) * 32 + c], -s_i2s[(2*h+1) * 32 + c]);
            }
        }
    }

    // ---- final outputs ----
    out_main[(size_t)n * 544 + tid] = s_mu[(tid & 15) * 32 + (tid >> 4)];
    if (tid < 32) out_main[(size_t)n * 544 + 512 + tid] = s_aout[tid];
}

extern "C" void kernel_launch(void* const* d_in, const int* in_sizes, int n_in,
                              void* d_out, int out_size) {
    const float* x  = (const float*)d_in[0];
    const float* Wt = (const float*)d_in[1];
    const float* bu = (const float*)d_in[2];
    const float* ba = (const float*)d_in[3];
    float* out  = (float*)d_out;
    float* outr = out + (size_t)2 * 254 * 544;

    const int smem_bytes = SMEM_FLOATS * 4;
    cudaFuncSetAttribute(emcaps_kernel, cudaFuncAttributeMaxDynamicSharedMemorySize, smem_bytes);
    emcaps_kernel<<<508, NTH, smem_bytes>>>(x, Wt, bu, ba, out, outr);
}

// round 7
// speedup vs baseline: 2.6654x; 1.2299x over previous
#include <cuda_runtime.h>
#include <math.h>

#define EPSF    1e-8f
#define LAMBDAF 1e-3f
#define NTH 512
#define NW  16
#define BPW 18    // 288 / 16 warps

// smem floats: xr 4608 | fac 288 | p1 8192 | p2 8192 | prs 512 | mu 512 | i2s 512 | lna 32 | aout 32
#define SMEM_FLOATS (4608 + 288 + 8192 + 8192 + 512 + 512 + 512 + 32 + 32)

typedef unsigned long long u64t;

// transposed weights: W2[B][j][c] as 16-byte chunks, index = B*128 + j*32 + c
__device__ uint4 g_w2[288 * 128];

__device__ __forceinline__ u64t pack2(float a, float b) {
    u64t r; asm("mov.b64 %0,{%1,%2};" : "=l"(r) : "f"(a), "f"(b)); return r;
}
__device__ __forceinline__ u64t dup2(float a) { return pack2(a, a); }
__device__ __forceinline__ void unpack2(u64t v, float& a, float& b) {
    asm("mov.b64 {%0,%1},%2;" : "=f"(a), "=f"(b) : "l"(v));
}
__device__ __forceinline__ u64t fma2(u64t a, u64t b, u64t c) {
    u64t d; asm("fma.rn.f32x2 %0,%1,%2,%3;" : "=l"(d) : "l"(a), "l"(b), "l"(c)); return d;
}
__device__ __forceinline__ u64t mul2(u64t a, u64t b) {
    u64t d; asm("mul.rn.f32x2 %0,%1,%2;" : "=l"(d) : "l"(a), "l"(b)); return d;
}
__device__ __forceinline__ u64t add2(u64t a, u64t b) {
    u64t d; asm("add.rn.f32x2 %0,%1,%2;" : "=l"(d) : "l"(a), "l"(b)); return d;
}

// warp max of f32 via monotonic u32 key + redux.sync.max.u32
__device__ __forceinline__ float warp_max_f32(float v) {
    unsigned int b = __float_as_uint(v);
    unsigned int key = (b & 0x80000000u) ? ~b : (b | 0x80000000u);
    unsigned int m;
    asm("redux.sync.max.u32 %0, %1, 0xffffffff;" : "=r"(m) : "r"(key));
    unsigned int mb = (m & 0x80000000u) ? (m & 0x7fffffffu) : ~m;
    return __uint_as_float(mb);
}

__device__ __forceinline__ unsigned int warp_add_u32(unsigned int v) {
    unsigned int s;
    asm("redux.sync.add.u32 %0, %1, 0xffffffff;" : "=r"(s) : "r"(v));
    return s;
}

// one-time (per launch) W transpose: out[B*128 + j*32 + c] = in[(B*32+c)*4 + j]
__global__ void transpose_w_kernel(const uint4* __restrict__ win) {
    int idx = blockIdx.x * blockDim.x + threadIdx.x;
    if (idx >= 288 * 128) return;
    int B   = idx >> 7;
    int rem = idx & 127;
    int j   = rem >> 5;
    int c   = rem & 31;
    g_w2[idx] = win[(size_t)(B * 32 + c) * 4 + j];
}

__global__ void __launch_bounds__(NTH, 1)
emcaps_kernel(const float* __restrict__ x,
              const float* __restrict__ beta_u,
              const float* __restrict__ beta_a,
              float* __restrict__ out_main,
              float* __restrict__ out_r)
{
    extern __shared__ float sm[];
    float* s_xr   = sm;               // [9*512]  patch matrices
    float* s_fac  = s_xr  + 4608;     // [288]    a_in/(a_in+eps)
    float* s_p1   = s_fac + 288;      // [16*512] per-warp partials Σ r2*v
    float* s_p2   = s_p1  + 8192;     // [16*512] per-warp partials Σ r2*v^2
    float* s_prs  = s_p2  + 8192;     // [16*32]  per-warp partials Σ r2
    float* s_mu   = s_prs + 512;      // [512] layout [p][c]
    float* s_i2s  = s_mu  + 512;      // [512] 1/(2 sigma) [p][c]
    float* s_lna  = s_i2s + 512;      // [32]
    float* s_aout = s_lna + 32;       // [32]

    const int n   = blockIdx.x;       // 508
    const int tid = threadIdx.x;
    const int w   = tid >> 5;
    const int c   = tid & 31;

    // ---- load the 9 patch rows: g = 9n+q -> x[b, k1+j, 0, :] ----
    for (int idx = tid; idx < 9 * 544; idx += NTH) {
        int q  = idx / 544;
        int rr = idx - q * 544;
        int g  = n * 9 + q;
        int b  = g / 2286;
        int k1 = (g - b * 2286) / 762;
        int j  = g % 254;
        const float* row = x + (size_t)((b * 256 + (k1 + j)) * 4) * 544;  // h = 0
        float val = row[rr];
        if (rr < 512) s_xr[q * 512 + rr] = val;
        else          s_fac[q * 32 + rr - 512] = val / (val + EPSF);
    }
    __syncthreads();

    u64t nmu2[8], ni2s2[8];
    float lnac = 0.f;
    #pragma unroll
    for (int h = 0; h < 8; ++h) { nmu2[h] = 0ull; ni2s2[h] = 0ull; }

    // coalesced W walk in transposed layout: element = 16 B; lane c at base + j*32 + c
    const ulonglong2* w2 = reinterpret_cast<const ulonglong2*>(g_w2);
    const ulonglong2* wp0 = w2 + (size_t)(w * BPW) * 128 + c;

    for (int s = 0; s < 3; ++s) {
        u64t acc1[8], acc2[8];
        #pragma unroll
        for (int h = 0; h < 8; ++h) { acc1[h] = 0ull; acc2[h] = 0ull; }
        float prs = 0.f;

        const ulonglong2* wp = wp0;
        ulonglong2 a0 = wp[0], a1 = wp[32], a2 = wp[64], a3 = wp[96];

        #pragma unroll 2
        for (int bi = 0; bi < BPW; ++bi) {
            int B = w * BPW + bi;

            // prefetch next bi's W (coalesced) before the compute tail
            ulonglong2 b0, b1, b2, b3;
            if (bi + 1 < BPW) {
                const ulonglong2* wn = wp + 128;
                b0 = wn[0]; b1 = wn[32]; b2 = wn[64]; b3 = wn[96];
            } else {
                b0 = a0; b1 = a1; b2 = a2; b3 = a3;
            }

            const float4* xp4 = reinterpret_cast<const float4*>(s_xr + B * 16);

            u64t vp[8];
            #pragma unroll
            for (int i = 0; i < 4; ++i) {
                float4 xi = xp4[i];
                u64t x0 = dup2(xi.x), x1 = dup2(xi.y), x2 = dup2(xi.z), x3 = dup2(xi.w);
                u64t lo = mul2(x0, a0.x);
                lo = fma2(x1, a1.x, lo);
                lo = fma2(x2, a2.x, lo);
                lo = fma2(x3, a3.x, lo);
                u64t hi = mul2(x0, a0.y);
                hi = fma2(x1, a1.y, hi);
                hi = fma2(x2, a2.y, hi);
                hi = fma2(x3, a3.y, hi);
                vp[2*i]   = lo;   // p = 4i+0, 4i+1
                vp[2*i+1] = hi;   // p = 4i+2, 4i+3
            }

            float r2;
            if (s == 0) {
                r2 = s_fac[B] * (1.0f / 32.0f);
            } else {
                u64t sc2 = 0ull;
                #pragma unroll
                for (int h = 0; h < 8; ++h) {
                    u64t d  = add2(vp[h], nmu2[h]);   // v - mu
                    u64t dd = mul2(d, d);
                    sc2 = fma2(dd, ni2s2[h], sc2);    // -= d^2 / (2 sigma)
                }
                float sl, sh;
                unpack2(sc2, sl, sh);
                float sc = lnac + sl + sh;
                float m  = warp_max_f32(sc);
                float e  = __expf(sc - m);
                // fixed-point warp sum: e in (0,1], q <= 2^24, sum <= 2^29
                unsigned int q  = __float2uint_rn(e * 16777216.f);
                unsigned int du = warp_add_u32(q);
                float r  = __fdividef(__uint2float_rn(q), __uint2float_rn(du));
                if (s == 2) out_r[(size_t)n * 9216 + B * 32 + c] = r;
                r2 = r * s_fac[B];
            }

            prs += r2;
            u64t r2p = dup2(r2);
            #pragma unroll
            for (int h = 0; h < 8; ++h) {
                u64t t = mul2(r2p, vp[h]);
                acc1[h] = add2(acc1[h], t);
                acc2[h] = fma2(t, vp[h], acc2[h]);
            }

            a0 = b0; a1 = b1; a2 = b2; a3 = b3;
            wp += 128;
        }

        // store per-warp partials
        {
            ulonglong2* p1v = reinterpret_cast<ulonglong2*>(s_p1 + w * 512 + c * 16);
            ulonglong2* p2v = reinterpret_cast<ulonglong2*>(s_p2 + w * 512 + c * 16);
            #pragma unroll
            for (int i = 0; i < 4; ++i) {
                p1v[i] = make_ulonglong2(acc1[2*i], acc1[2*i+1]);
                p2v[i] = make_ulonglong2(acc2[2*i], acc2[2*i+1]);
            }
            s_prs[w * 32 + c] = prs;
        }
        __syncthreads();

        // ============ reduce partials -> mu / sigma / a_out ============
        {
            int cp = tid;                 // cp = c2*16 + p
            int c2 = cp >> 4, p = cp & 15;
            float e1 = 0.f, e2 = 0.f, rs = 0.f;
            #pragma unroll
            for (int ww = 0; ww < NW; ++ww) {
                e1 += s_p1[ww * 512 + cp];
                e2 += s_p2[ww * 512 + cp];
                rs += s_prs[ww * 32 + c2];
            }
            float invr = 1.0f / (rs + EPSF);
            float S    = rs * invr;
            float mu   = e1 * invr;
            float E2   = e2 * invr;
            float var  = E2 - mu * mu * (2.0f - S);
            float sig  = fmaxf(var, 0.f) + EPSF;
            float hls  = 0.5f * __logf(sig);
            s_mu [p * 32 + c2] = mu;
            s_i2s[p * 32 + c2] = 0.5f / sig;
            float hsum = hls;
            #pragma unroll
            for (int o = 8; o; o >>= 1) hsum += __shfl_xor_sync(0xffffffffu, hsum, o, 16);
            if (p == 0) {
                float cost = rs * (16.f * beta_u[c2] + hsum);
                float av   = 1.0f / (1.0f + __expf(-LAMBDAF * (beta_a[c2] - cost)));
                s_aout[c2] = av;
                s_lna [c2] = __logf(av) - hsum;
            }
        }
        __syncthreads();

        if (s < 2) {
            lnac = s_lna[c];
            #pragma unroll
            for (int h = 0; h < 8; ++h) {
                nmu2 [h] = pack2(-s_mu [(2*h) * 32 + c], -s_mu [(2*h+1) * 32 + c]);
                ni2s2[h] = pack2(-s_i2s[(2*h) * 32 + c], -s_i2s[(2*h+1) * 32 + c]);
            }
        }
    }

    // ---- final outputs ----
    out_main[(size_t)n * 544 + tid] = s_mu[(tid & 15) * 32 + (tid >> 4)];
    if (tid < 32) out_main[(size_t)n * 544 + 512 + tid] = s_aout[tid];
}

extern "C" void kernel_launch(void* const* d_in, const int* in_sizes, int n_in,
                              void* d_out, int out_size) {
    const float* x  = (const float*)d_in[0];
    const float* Wt = (const float*)d_in[1];
    const float* bu = (const float*)d_in[2];
    const float* ba = (const float*)d_in[3];
    float* out  = (float*)d_out;
    float* outr = out + (size_t)2 * 254 * 544;

    transpose_w_kernel<<<(288 * 128 + 255) / 256, 256>>>((const uint4*)Wt);

    const int smem_bytes = SMEM_FLOATS * 4;
    cudaFuncSetAttribute(emcaps_kernel, cudaFuncAttributeMaxDynamicSharedMemorySize, smem_bytes);
    emcaps_kernel<<<508, NTH, smem_bytes>>>(x, bu, ba, out, outr);
}

// round 8
// speedup vs baseline: 2.9593x; 1.1102x over previous
#include <cuda_runtime.h>
#include <math.h>

#define EPSF    1e-8f
#define LAMBDAF 1e-3f
#define NTH 128
#define NW  4
#define BPW 72    // 288 / 4 warps

// smem floats: xr 4608 | fac 288 | p1 2048 | p2 2048 | prs 128 | mu 512 | i2s 512 | lna 32 | aout 32
#define SMEM_FLOATS (4608 + 288 + 2048 + 2048 + 128 + 512 + 512 + 32 + 32)

typedef unsigned long long u64t;

// transposed weights: W2[B][j][c] as 16-byte chunks, index = B*128 + j*32 + c
__device__ uint4 g_w2[288 * 128];

__device__ __forceinline__ u64t pack2(float a, float b) {
    u64t r; asm("mov.b64 %0,{%1,%2};" : "=l"(r) : "f"(a), "f"(b)); return r;
}
__device__ __forceinline__ u64t dup2(float a) { return pack2(a, a); }
__device__ __forceinline__ void unpack2(u64t v, float& a, float& b) {
    asm("mov.b64 {%0,%1},%2;" : "=f"(a), "=f"(b) : "l"(v));
}
__device__ __forceinline__ u64t fma2(u64t a, u64t b, u64t c) {
    u64t d; asm("fma.rn.f32x2 %0,%1,%2,%3;" : "=l"(d) : "l"(a), "l"(b), "l"(c)); return d;
}
__device__ __forceinline__ u64t mul2(u64t a, u64t b) {
    u64t d; asm("mul.rn.f32x2 %0,%1,%2;" : "=l"(d) : "l"(a), "l"(b)); return d;
}
__device__ __forceinline__ u64t add2(u64t a, u64t b) {
    u64t d; asm("add.rn.f32x2 %0,%1,%2;" : "=l"(d) : "l"(a), "l"(b)); return d;
}

// warp max of f32 via monotonic u32 key + redux.sync.max.u32
__device__ __forceinline__ float warp_max_f32(float v) {
    unsigned int b = __float_as_uint(v);
    unsigned int key = (b & 0x80000000u) ? ~b : (b | 0x80000000u);
    unsigned int m;
    asm("redux.sync.max.u32 %0, %1, 0xffffffff;" : "=r"(m) : "r"(key));
    unsigned int mb = (m & 0x80000000u) ? (m & 0x7fffffffu) : ~m;
    return __uint_as_float(mb);
}

__device__ __forceinline__ unsigned int warp_add_u32(unsigned int v) {
    unsigned int s;
    asm("redux.sync.add.u32 %0, %1, 0xffffffff;" : "=r"(s) : "r"(v));
    return s;
}

// one-time (per launch) W transpose: out[B*128 + j*32 + c] = in[(B*32+c)*4 + j]
__global__ void transpose_w_kernel(const uint4* __restrict__ win) {
    int idx = blockIdx.x * blockDim.x + threadIdx.x;
    if (idx >= 288 * 128) return;
    int B   = idx >> 7;
    int rem = idx & 127;
    int j   = rem >> 5;
    int c   = rem & 31;
    g_w2[idx] = win[(size_t)(B * 32 + c) * 4 + j];
}

__global__ void __launch_bounds__(NTH, 4)
emcaps_kernel(const float* __restrict__ x,
              const float* __restrict__ beta_u,
              const float* __restrict__ beta_a,
              float* __restrict__ out_main,
              float* __restrict__ out_r)
{
    extern __shared__ float sm[];
    float* s_xr   = sm;               // [9*512]  patch matrices
    float* s_fac  = s_xr  + 4608;     // [288]    a_in/(a_in+eps)
    float* s_p1   = s_fac + 288;      // [4*512]  per-warp partials Σ r2*v
    float* s_p2   = s_p1  + 2048;     // [4*512]  per-warp partials Σ r2*v^2
    float* s_prs  = s_p2  + 2048;     // [4*32]   per-warp partials Σ r2
    float* s_mu   = s_prs + 128;      // [512] layout [p][c]
    float* s_i2s  = s_mu  + 512;      // [512] 1/(2 sigma) [p][c]
    float* s_lna  = s_i2s + 512;      // [32]
    float* s_aout = s_lna + 32;       // [32]

    const int n   = blockIdx.x;       // 508
    const int tid = threadIdx.x;
    const int w   = tid >> 5;         // 0..3
    const int c   = tid & 31;

    // ---- load the 9 patch rows: g = 9n+q -> x[b, k1+j, 0, :] ----
    for (int idx = tid; idx < 9 * 544; idx += NTH) {
        int q  = idx / 544;
        int rr = idx - q * 544;
        int g  = n * 9 + q;
        int b  = g / 2286;
        int k1 = (g - b * 2286) / 762;
        int j  = g % 254;
        const float* row = x + (size_t)((b * 256 + (k1 + j)) * 4) * 544;  // h = 0
        float val = row[rr];
        if (rr < 512) s_xr[q * 512 + rr] = val;
        else          s_fac[q * 32 + rr - 512] = val / (val + EPSF);
    }
    __syncthreads();

    u64t nmu2[8], ni2s2[8];
    float lnac = 0.f;
    #pragma unroll
    for (int h = 0; h < 8; ++h) { nmu2[h] = 0ull; ni2s2[h] = 0ull; }

    // coalesced W walk in transposed layout: element = 16 B; lane c at base + j*32 + c
    const ulonglong2* w2 = reinterpret_cast<const ulonglong2*>(g_w2);
    const ulonglong2* wp0 = w2 + (size_t)(w * BPW) * 128 + c;

    for (int s = 0; s < 3; ++s) {
        u64t acc1[8], acc2[8];
        #pragma unroll
        for (int h = 0; h < 8; ++h) { acc1[h] = 0ull; acc2[h] = 0ull; }
        float prs = 0.f;

        const ulonglong2* wp = wp0;
        ulonglong2 a0 = wp[0], a1 = wp[32], a2 = wp[64], a3 = wp[96];

        #pragma unroll 2
        for (int bi = 0; bi < BPW; ++bi) {
            int B = w * BPW + bi;

            // prefetch next bi's W (coalesced) before the compute tail
            ulonglong2 b0, b1, b2, b3;
            if (bi + 1 < BPW) {
                const ulonglong2* wn = wp + 128;
                b0 = wn[0]; b1 = wn[32]; b2 = wn[64]; b3 = wn[96];
            } else {
                b0 = a0; b1 = a1; b2 = a2; b3 = a3;
            }

            const float4* xp4 = reinterpret_cast<const float4*>(s_xr + B * 16);

            u64t vp[8];
            #pragma unroll
            for (int i = 0; i < 4; ++i) {
                float4 xi = xp4[i];
                u64t x0 = dup2(xi.x), x1 = dup2(xi.y), x2 = dup2(xi.z), x3 = dup2(xi.w);
                u64t lo = mul2(x0, a0.x);
                lo = fma2(x1, a1.x, lo);
                lo = fma2(x2, a2.x, lo);
                lo = fma2(x3, a3.x, lo);
                u64t hi = mul2(x0, a0.y);
                hi = fma2(x1, a1.y, hi);
                hi = fma2(x2, a2.y, hi);
                hi = fma2(x3, a3.y, hi);
                vp[2*i]   = lo;   // p = 4i+0, 4i+1
                vp[2*i+1] = hi;   // p = 4i+2, 4i+3
            }

            float r2;
            if (s == 0) {
                r2 = s_fac[B] * (1.0f / 32.0f);
            } else {
                u64t sa = 0ull, sb = 0ull;       // 2 chains halve dep depth
                #pragma unroll
                for (int h = 0; h < 4; ++h) {
                    u64t d0 = add2(vp[2*h],   nmu2[2*h]);
                    u64t d1 = add2(vp[2*h+1], nmu2[2*h+1]);
                    sa = fma2(mul2(d0, d0), ni2s2[2*h],   sa);
                    sb = fma2(mul2(d1, d1), ni2s2[2*h+1], sb);
                }
                u64t sc2 = add2(sa, sb);
                float sl, sh;
                unpack2(sc2, sl, sh);
                float sc = lnac + sl + sh;
                float m  = warp_max_f32(sc);
                float e  = __expf(sc - m);
                // fixed-point warp sum: e in (0,1], q <= 2^24, sum <= 2^29
                unsigned int q  = __float2uint_rn(e * 16777216.f);
                unsigned int du = warp_add_u32(q);
                float r  = __fdividef(__uint2float_rn(q), __uint2float_rn(du));
                if (s == 2) out_r[(size_t)n * 9216 + B * 32 + c] = r;
                r2 = r * s_fac[B];
            }

            prs += r2;
            u64t r2p = dup2(r2);
            #pragma unroll
            for (int h = 0; h < 8; ++h) {
                u64t t = mul2(r2p, vp[h]);
                acc1[h] = add2(acc1[h], t);
                acc2[h] = fma2(t, vp[h], acc2[h]);
            }

            a0 = b0; a1 = b1; a2 = b2; a3 = b3;
            wp += 128;
        }

        // store per-warp partials
        {
            ulonglong2* p1v = reinterpret_cast<ulonglong2*>(s_p1 + w * 512 + c * 16);
            ulonglong2* p2v = reinterpret_cast<ulonglong2*>(s_p2 + w * 512 + c * 16);
            #pragma unroll
            for (int i = 0; i < 4; ++i) {
                p1v[i] = make_ulonglong2(acc1[2*i], acc1[2*i+1]);
                p2v[i] = make_ulonglong2(acc2[2*i], acc2[2*i+1]);
            }
            s_prs[w * 32 + c] = prs;
        }
        __syncthreads();

        // ============ reduce partials -> mu / sigma / a_out ============
        // 512 cp values over 128 threads: 4 per thread (same p lanes, different c2)
        #pragma unroll
        for (int k = 0; k < 4; ++k) {
            int cp = tid + k * 128;       // cp = c2*16 + p
            int c2 = cp >> 4, p = cp & 15;
            float e1 = 0.f, e2 = 0.f, rs = 0.f;
            #pragma unroll
            for (int ww = 0; ww < NW; ++ww) {
                e1 += s_p1[ww * 512 + cp];
                e2 += s_p2[ww * 512 + cp];
                rs += s_prs[ww * 32 + c2];
            }
            float invr = 1.0f / (rs + EPSF);
            float S    = rs * invr;
            float mu   = e1 * invr;
            float E2   = e2 * invr;
            float var  = E2 - mu * mu * (2.0f - S);
            float sig  = fmaxf(var, 0.f) + EPSF;
            float hls  = 0.5f * __logf(sig);
            s_mu [p * 32 + c2] = mu;
            s_i2s[p * 32 + c2] = 0.5f / sig;
            float hsum = hls;
            #pragma unroll
            for (int o = 8; o; o >>= 1) hsum += __shfl_xor_sync(0xffffffffu, hsum, o, 16);
            if (p == 0) {
                float cost = rs * (16.f * beta_u[c2] + hsum);
                float av   = 1.0f / (1.0f + __expf(-LAMBDAF * (beta_a[c2] - cost)));
                s_aout[c2] = av;
                s_lna [c2] = __logf(av) - hsum;
            }
        }
        __syncthreads();

        if (s < 2) {
            lnac = s_lna[c];
            #pragma unroll
            for (int h = 0; h < 8; ++h) {
                nmu2 [h] = pack2(-s_mu [(2*h) * 32 + c], -s_mu [(2*h+1) * 32 + c]);
                ni2s2[h] = pack2(-s_i2s[(2*h) * 32 + c], -s_i2s[(2*h+1) * 32 + c]);
            }
        }
    }

    // ---- final outputs ----
    #pragma unroll
    for (int k = 0; k < 4; ++k) {
        int i = tid + k * 128;
        out_main[(size_t)n * 544 + i] = s_mu[(i & 15) * 32 + (i >> 4)];
    }
    if (tid < 32) out_main[(size_t)n * 544 + 512 + tid] = s_aout[tid];
}

extern "C" void kernel_launch(void* const* d_in, const int* in_sizes, int n_in,
                              void* d_out, int out_size) {
    const float* x  = (const float*)d_in[0];
    const float* Wt = (const float*)d_in[1];
    const float* bu = (const float*)d_in[2];
    const float* ba = (const float*)d_in[3];
    float* out  = (float*)d_out;
    float* outr = out + (size_t)2 * 254 * 544;

    transpose_w_kernel<<<(288 * 128 + 255) / 256, 256>>>((const uint4*)Wt);

    const int smem_bytes = SMEM_FLOATS * 4;
    cudaFuncSetAttribute(emcaps_kernel, cudaFuncAttributeMaxDynamicSharedMemorySize, smem_bytes);
    emcaps_kernel<<<508, NTH, smem_bytes>>>(x, bu, ba, out, outr);
}